// round 13
// baseline (speedup 1.0000x reference)
#include <cuda_runtime.h>
#include <cuda_bf16.h>
#include <math.h>
#include <stdint.h>

#define BB 4
#define NSEQ 2048
#define CC 1024
#define HH 16
#define DD 64
#define MM (BB*NSEQ)

// ---------------- scratch (device globals; allocation-free rule) -----------
__device__ __align__(16) __nv_bfloat16 g_xv_h[(size_t)MM*CC];
__device__ __align__(16) __nv_bfloat16 g_xv_l[(size_t)MM*CC];
__device__ __align__(16) __nv_bfloat16 g_wq_h[(size_t)CC*CC];
__device__ __align__(16) __nv_bfloat16 g_wq_l[(size_t)CC*CC];
__device__ __align__(16) __nv_bfloat16 g_wk_h[(size_t)CC*CC];
__device__ __align__(16) __nv_bfloat16 g_wk_l[(size_t)CC*CC];
__device__ __align__(16) __nv_bfloat16 g_wp_h[(size_t)CC*CC];
__device__ __align__(16) __nv_bfloat16 g_wp_l[(size_t)CC*CC];
__device__ __align__(16) __nv_bfloat16 g_q_h[(size_t)MM*CC];
__device__ __align__(16) __nv_bfloat16 g_q_l[(size_t)MM*CC];
__device__ __align__(16) __nv_bfloat16 g_k_h[(size_t)MM*CC];
__device__ __align__(16) __nv_bfloat16 g_k_l[(size_t)MM*CC];
__device__ __align__(16) __nv_bfloat16 g_vt_h[(size_t)CC*MM];
__device__ __align__(16) __nv_bfloat16 g_vt_l[(size_t)CC*MM];
__device__ __align__(16) __nv_bfloat16 g_o_h[(size_t)MM*CC];
__device__ __align__(16) __nv_bfloat16 g_o_l[(size_t)MM*CC];

// ---------------- helpers ---------------------------------------------------
__device__ __forceinline__ void split1(float v, __nv_bfloat16& h, __nv_bfloat16& l) {
    h = __float2bfloat16(v);
    l = __float2bfloat16(v - __bfloat162float(h));
}

#define MMA(c,a,b) asm volatile( \
  "mma.sync.aligned.m16n8k16.row.col.f32.bf16.bf16.f32 " \
  "{%0,%1,%2,%3},{%4,%5,%6,%7},{%8,%9},{%0,%1,%2,%3};\n" \
  : "+f"((c)[0]),"+f"((c)[1]),"+f"((c)[2]),"+f"((c)[3]) \
  : "r"((a)[0]),"r"((a)[1]),"r"((a)[2]),"r"((a)[3]),"r"((b)[0]),"r"((b)[1]))

#define LDSM4(R0,R1,R2,R3,ADDR) asm volatile( \
  "ldmatrix.sync.aligned.m8n8.x4.shared.b16 {%0,%1,%2,%3},[%4];\n" \
  : "=r"(R0),"=r"(R1),"=r"(R2),"=r"(R3) : "r"(ADDR))

__device__ __forceinline__ void cpa16(uint32_t d, const void* s) {
    asm volatile("cp.async.cg.shared.global [%0], [%1], 16;\n" :: "r"(d), "l"(s));
}
#define CP_COMMIT() asm volatile("cp.async.commit_group;\n")
#define CP_WAIT1()  asm volatile("cp.async.wait_group 1;\n")
#define CP_WAIT0()  asm volatile("cp.async.wait_group 0;\n")

__device__ __forceinline__ uint32_t s2u(const void* p) {
    uint32_t a;
    asm("{ .reg .u64 t; cvta.to.shared.u64 t, %1; cvt.u32.u64 %0, t; }" : "=r"(a) : "l"(p));
    return a;
}

// ---------------- fp32 -> hi/lo bf16 convert --------------------------------
__global__ void conv_split(const float4* __restrict__ src,
                           __nv_bfloat162* __restrict__ h,
                           __nv_bfloat162* __restrict__ l, int n4)
{
    int i = blockIdx.x * blockDim.x + threadIdx.x;
    if (i >= n4) return;
    float4 v = src[i];
    __nv_bfloat162 h0, h1, l0, l1;
    split1(v.x, h0.x, l0.x); split1(v.y, h0.y, l0.y);
    split1(v.z, h1.x, l1.x); split1(v.w, h1.y, l1.y);
    h[(size_t)i*2]   = h0; h[(size_t)i*2+1] = h1;
    l[(size_t)i*2]   = l0; l[(size_t)i*2+1] = l1;
}

// ---------------------------------------------------------------------------
// bf16x3-split GEMM: C = epi(alpha * A @ B^T), A [M,K], B [N,K] (both K-major).
// A either pre-split planes (CONVA=0) or fp32 split at fill (CONVA=1).
// EPI: 0 = fp32 C (+bias), 1 = hi/lo plane C, 2 = sigmoid -> fp32 C.
// BM=128, 256 threads, warps 4x2, double-buffered cp.async, ldmatrix frags.
// ---------------------------------------------------------------------------
template<int BN, int EPI, int CONVA>
__global__ void __launch_bounds__(256, 2)
gemm_bf16x3(const __nv_bfloat16* __restrict__ Ahg, const __nv_bfloat16* __restrict__ Alg,
            const float* __restrict__ Afg, int lda, long aBS, long aHS,
            const __nv_bfloat16* __restrict__ Bhg, const __nv_bfloat16* __restrict__ Blg,
            int ldb, long bBS, long bHS,
            float* __restrict__ Cf, __nv_bfloat16* __restrict__ Ch,
            __nv_bfloat16* __restrict__ Cl, int ldc, long cBS, long cHS,
            int K, float alpha, const float* __restrict__ bias)
{
    constexpr int BM = 128;
    constexpr int SROW = 80;                    // bytes per 32-bf16 smem row
    constexpr int APL = BM * SROW;              // one A plane
    constexpr int BPL = BN * SROW;
    constexpr int PAH = 0, PAL = APL, PBH = 2*APL, PBL = 2*APL + BPL;
    constexpr int STG = 2*APL + 2*BPL;          // bytes per stage
    constexpr int WM = 32, WN = BN / 2;
    constexpr int MI = WM / 16, NJ = WN / 8;
    extern __shared__ uint8_t smem[];
    const uint32_t sb = s2u(smem);

    const int t = threadIdx.x, wid = t >> 5, lane = t & 31;
    const int wm = wid >> 1, wn = wid & 1;
    const int grp = lane >> 2, qid = lane & 3;

    const int z = blockIdx.z, zb = z / HH, zh = z % HH;
    const size_t aOff = (size_t)zb * aBS + (size_t)zh * aHS;
    const __nv_bfloat16* Ah = Ahg + aOff;
    const __nv_bfloat16* Al = Alg + aOff;
    const float*         Af = Afg + aOff;
    const __nv_bfloat16* Bh = Bhg + (size_t)zb * bBS + (size_t)zh * bHS;
    const __nv_bfloat16* Bl = Blg + (size_t)zb * bBS + (size_t)zh * bHS;
    const size_t cOff = (size_t)zb * cBS + (size_t)zh * cHS;

    const int bm = blockIdx.y * BM;
    const int bn = blockIdx.x * BN;

    // ldmatrix per-lane indices
    const int aRow  = (lane & 7) + ((lane >> 3) & 1) * 8;
    const int aHalf = lane >> 4;
    const int bRow  = ((lane >> 4) << 3) + (lane & 7);
    const int bHalf = (lane >> 3) & 1;

    float acc[MI][NJ][4];
    #pragma unroll
    for (int i = 0; i < MI; i++)
        #pragma unroll
        for (int j = 0; j < NJ; j++)
            #pragma unroll
            for (int c = 0; c < 4; c++) acc[i][j][c] = 0.f;

    auto fill = [&](int kt, int s) {
        const uint32_t sB = sb + s * STG;
        if (CONVA) {
            // fp32 A: load float4, split, STS 8B per plane
            #pragma unroll
            for (int it = 0; it < 4; it++) {
                int idx = it * 256 + t;
                int r = idx >> 3, q = idx & 7;
                float4 v = *(const float4*)(Af + (size_t)(bm + r) * lda + kt * 32 + q * 4);
                __nv_bfloat162 h0, h1, l0, l1;
                split1(v.x, h0.x, l0.x); split1(v.y, h0.y, l0.y);
                split1(v.z, h1.x, l1.x); split1(v.w, h1.y, l1.y);
                uint8_t* ph = smem + s * STG + PAH + r * SROW + q * 8;
                uint8_t* pl = smem + s * STG + PAL + r * SROW + q * 8;
                ((__nv_bfloat162*)ph)[0] = h0; ((__nv_bfloat162*)ph)[1] = h1;
                ((__nv_bfloat162*)pl)[0] = l0; ((__nv_bfloat162*)pl)[1] = l1;
            }
        } else {
            #pragma unroll
            for (int it = 0; it < 2; it++) {
                int idx = it * 256 + t;
                int r = idx >> 2, c = idx & 3;
                size_t g = ((size_t)(bm + r) * lda + kt * 32) * 2 + c * 16;
                uint32_t sm = r * SROW + c * 16;
                cpa16(sB + PAH + sm, (const uint8_t*)Ah + g);
                cpa16(sB + PAL + sm, (const uint8_t*)Al + g);
            }
        }
        #pragma unroll
        for (int it = 0; it < (BN * 4) / 256; it++) {
            int idx = it * 256 + t;
            int r = idx >> 2, c = idx & 3;
            size_t g = ((size_t)(bn + r) * ldb + kt * 32) * 2 + c * 16;
            uint32_t sm = r * SROW + c * 16;
            cpa16(sB + PBH + sm, (const uint8_t*)Bh + g);
            cpa16(sB + PBL + sm, (const uint8_t*)Bl + g);
        }
    };

    auto compute = [&](int s) {
        const uint32_t sB = sb + s * STG;
        const uint32_t aBase = sB + (wm * WM + aRow) * SROW + aHalf * 16;
        const uint32_t bBase = sB + (wn * WN + bRow) * SROW + bHalf * 16;
        #pragma unroll
        for (int kb = 0; kb < 32; kb += 16) {
            const uint32_t kof = kb * 2;
            uint32_t ah[MI][4], al[MI][4], bx[NJ][2];
            #pragma unroll
            for (int i = 0; i < MI; i++)
                LDSM4(ah[i][0], ah[i][1], ah[i][2], ah[i][3],
                      aBase + PAH + i * 16 * SROW + kof);
            #pragma unroll
            for (int jg = 0; jg < NJ / 2; jg++)
                LDSM4(bx[2*jg][0], bx[2*jg][1], bx[2*jg+1][0], bx[2*jg+1][1],
                      bBase + PBH + jg * 16 * SROW + kof);
            #pragma unroll
            for (int i = 0; i < MI; i++)
                #pragma unroll
                for (int j = 0; j < NJ; j++) MMA(acc[i][j], ah[i], bx[j]);
            #pragma unroll
            for (int i = 0; i < MI; i++)
                LDSM4(al[i][0], al[i][1], al[i][2], al[i][3],
                      aBase + PAL + i * 16 * SROW + kof);
            #pragma unroll
            for (int i = 0; i < MI; i++)
                #pragma unroll
                for (int j = 0; j < NJ; j++) MMA(acc[i][j], al[i], bx[j]);
            #pragma unroll
            for (int jg = 0; jg < NJ / 2; jg++)
                LDSM4(bx[2*jg][0], bx[2*jg][1], bx[2*jg+1][0], bx[2*jg+1][1],
                      bBase + PBL + jg * 16 * SROW + kof);
            #pragma unroll
            for (int i = 0; i < MI; i++)
                #pragma unroll
                for (int j = 0; j < NJ; j++) MMA(acc[i][j], ah[i], bx[j]);
        }
    };

    const int KT = K >> 5;
    fill(0, 0);
    CP_COMMIT();
    for (int kt = 0; kt < KT; kt++) {
        int s = kt & 1;
        if (kt + 1 < KT) { fill(kt + 1, s ^ 1); CP_COMMIT(); CP_WAIT1(); }
        else             { CP_WAIT0(); }
        __syncthreads();
        compute(s);
        __syncthreads();
    }

    // ---- epilogue ----
    #pragma unroll
    for (int i = 0; i < MI; i++) {
        int r0 = bm + wm * WM + i * 16 + grp;
        #pragma unroll
        for (int j = 0; j < NJ; j++) {
            int c0 = bn + wn * WN + j * 8 + qid * 2;
            float v0 = acc[i][j][0] * alpha;
            float v1 = acc[i][j][1] * alpha;
            float v2 = acc[i][j][2] * alpha;
            float v3 = acc[i][j][3] * alpha;
            if (EPI == 2) {
                v0 = 1.f / (1.f + __expf(-v0));
                v1 = 1.f / (1.f + __expf(-v1));
                v2 = 1.f / (1.f + __expf(-v2));
                v3 = 1.f / (1.f + __expf(-v3));
            }
            if (EPI == 0 && bias) {
                float b0 = bias[c0], b1 = bias[c0 + 1];
                v0 += b0; v1 += b1; v2 += b0; v3 += b1;
            }
            if (EPI == 0 || EPI == 2) {
                float* p0 = Cf + cOff + (size_t)r0 * ldc + c0;
                float* p1 = Cf + cOff + (size_t)(r0 + 8) * ldc + c0;
                p0[0] = v0; p0[1] = v1; p1[0] = v2; p1[1] = v3;
            }
            if (EPI == 1) {
                __nv_bfloat162 h0, l0, h1, l1;
                split1(v0, h0.x, l0.x); split1(v1, h0.y, l0.y);
                split1(v2, h1.x, l1.x); split1(v3, h1.y, l1.y);
                size_t o0 = cOff + (size_t)r0 * ldc + c0;
                size_t o1 = cOff + (size_t)(r0 + 8) * ldc + c0;
                *(__nv_bfloat162*)(Ch + o0) = h0;
                *(__nv_bfloat162*)(Cl + o0) = l0;
                *(__nv_bfloat162*)(Ch + o1) = h1;
                *(__nv_bfloat162*)(Cl + o1) = l1;
            }
        }
    }
}

// ---------------------------------------------------------------------------
extern "C" void kernel_launch(void* const* d_in, const int* in_sizes, int n_in,
                              void* d_out, int out_size)
{
    const float* x_q = (const float*)d_in[0];
    const float* x_k = (const float*)d_in[1];
    const float* x_v = (const float*)d_in[2];
    const float* Wq  = (const float*)d_in[3];
    const float* Wk  = (const float*)d_in[4];
    const float* Wv  = (const float*)d_in[5];
    const float* Wp  = (const float*)d_in[6];
    const float* bp  = (const float*)d_in[7];

    __nv_bfloat16 *xvh, *xvl, *wqh, *wql, *wkh, *wkl, *wph, *wpl;
    __nv_bfloat16 *qh, *ql, *kh, *kl, *vth, *vtl, *oh, *ol;
    cudaGetSymbolAddress((void**)&xvh, g_xv_h); cudaGetSymbolAddress((void**)&xvl, g_xv_l);
    cudaGetSymbolAddress((void**)&wqh, g_wq_h); cudaGetSymbolAddress((void**)&wql, g_wq_l);
    cudaGetSymbolAddress((void**)&wkh, g_wk_h); cudaGetSymbolAddress((void**)&wkl, g_wk_l);
    cudaGetSymbolAddress((void**)&wph, g_wp_h); cudaGetSymbolAddress((void**)&wpl, g_wp_l);
    cudaGetSymbolAddress((void**)&qh,  g_q_h);  cudaGetSymbolAddress((void**)&ql,  g_q_l);
    cudaGetSymbolAddress((void**)&kh,  g_k_h);  cudaGetSymbolAddress((void**)&kl,  g_k_l);
    cudaGetSymbolAddress((void**)&vth, g_vt_h); cudaGetSymbolAddress((void**)&vtl, g_vt_l);
    cudaGetSymbolAddress((void**)&oh,  g_o_h);  cudaGetSymbolAddress((void**)&ol,  g_o_l);

    float* out  = (float*)d_out;
    float* attn = out + (size_t)MM * CC;

    const int SM128 = 2 * (2 * 128 * 80 + 2 * 128 * 80);  // 81920
    const int SM64  = 2 * (2 * 128 * 80 + 2 * 64  * 80);  // 61440
    cudaFuncSetAttribute(gemm_bf16x3<128,1,1>, cudaFuncAttributeMaxDynamicSharedMemorySize, SM128);
    cudaFuncSetAttribute(gemm_bf16x3<128,2,0>, cudaFuncAttributeMaxDynamicSharedMemorySize, SM128);
    cudaFuncSetAttribute(gemm_bf16x3<64, 1,1>, cudaFuncAttributeMaxDynamicSharedMemorySize, SM64);
    cudaFuncSetAttribute(gemm_bf16x3<128,0,0>, cudaFuncAttributeMaxDynamicSharedMemorySize, SM128);

    dim3 blk(256);

    // input conversions (B-side operands need bf16 planes)
    {
        int n4x = (MM * CC) / 4, n4w = (CC * CC) / 4;
        conv_split<<<(n4x + 255) / 256, 256>>>((const float4*)x_v,
            (__nv_bfloat162*)xvh, (__nv_bfloat162*)xvl, n4x);
        conv_split<<<(n4w + 255) / 256, 256>>>((const float4*)Wq,
            (__nv_bfloat162*)wqh, (__nv_bfloat162*)wql, n4w);
        conv_split<<<(n4w + 255) / 256, 256>>>((const float4*)Wk,
            (__nv_bfloat162*)wkh, (__nv_bfloat162*)wkl, n4w);
        conv_split<<<(n4w + 255) / 256, 256>>>((const float4*)Wp,
            (__nv_bfloat162*)wph, (__nv_bfloat162*)wpl, n4w);
    }

    // q = x_q @ Wq^T  (A fp32 split-at-fill, out planes)
    gemm_bf16x3<128,1,1><<<dim3(CC/128, MM/128, 1), blk, SM128>>>(
        nullptr, nullptr, x_q, CC, 0, 0, wqh, wql, CC, 0, 0,
        nullptr, qh, ql, CC, 0, 0, CC, 1.f, nullptr);
    // k = x_k @ Wk^T
    gemm_bf16x3<128,1,1><<<dim3(CC/128, MM/128, 1), blk, SM128>>>(
        nullptr, nullptr, x_k, CC, 0, 0, wkh, wkl, CC, 0, 0,
        nullptr, kh, kl, CC, 0, 0, CC, 1.f, nullptr);
    // vt = Wv @ x_v^T  (= v^T, [CC x MM])
    gemm_bf16x3<128,1,1><<<dim3(MM/128, CC/128, 1), blk, SM128>>>(
        nullptr, nullptr, Wv, CC, 0, 0, xvh, xvl, CC, 0, 0,
        nullptr, vth, vtl, MM, 0, 0, CC, 1.f, nullptr);

    // attn = sigmoid(q k^T / 8) per head -> fp32 d_out
    gemm_bf16x3<128,2,0><<<dim3(NSEQ/128, NSEQ/128, BB*HH), blk, SM128>>>(
        qh, ql, nullptr, CC, (long)NSEQ*CC, DD,
        kh, kl, CC, (long)NSEQ*CC, DD,
        attn, nullptr, nullptr, NSEQ, (long)HH*NSEQ*NSEQ, (long)NSEQ*NSEQ,
        DD, 0.125f, nullptr);

    // o = attn @ vt^T per head (A = attn fp32 split-at-fill, B = vt planes)
    gemm_bf16x3<64,1,1><<<dim3(1, NSEQ/128, BB*HH), blk, SM64>>>(
        nullptr, nullptr, attn, NSEQ, (long)HH*NSEQ*NSEQ, (long)NSEQ*NSEQ,
        vth, vtl, MM, NSEQ, (long)DD*MM,
        nullptr, oh, ol, CC, (long)NSEQ*CC, DD, NSEQ, 1.f, nullptr);

    // out = o @ Wp^T + bp
    gemm_bf16x3<128,0,0><<<dim3(CC/128, MM/128, 1), blk, SM128>>>(
        oh, ol, nullptr, CC, 0, 0, wph, wpl, CC, 0, 0,
        out, nullptr, nullptr, CC, 0, 0, CC, 1.f, bp);
}

// round 14
// speedup vs baseline: 1.0023x; 1.0023x over previous
#include <cuda_runtime.h>
#include <cuda_bf16.h>
#include <math.h>
#include <stdint.h>

#define BB 4
#define NSEQ 2048
#define CC 1024
#define HH 16
#define DD 64
#define MM (BB*NSEQ)

// ---------------- scratch (device globals; allocation-free rule) -----------
__device__ __align__(16) __nv_bfloat16 g_xv_h[(size_t)MM*CC];
__device__ __align__(16) __nv_bfloat16 g_xv_l[(size_t)MM*CC];
__device__ __align__(16) __nv_bfloat16 g_wq_h[(size_t)CC*CC];
__device__ __align__(16) __nv_bfloat16 g_wq_l[(size_t)CC*CC];
__device__ __align__(16) __nv_bfloat16 g_wk_h[(size_t)CC*CC];
__device__ __align__(16) __nv_bfloat16 g_wk_l[(size_t)CC*CC];
__device__ __align__(16) __nv_bfloat16 g_wp_h[(size_t)CC*CC];
__device__ __align__(16) __nv_bfloat16 g_wp_l[(size_t)CC*CC];
__device__ __align__(16) __nv_bfloat16 g_q_h[(size_t)MM*CC];
__device__ __align__(16) __nv_bfloat16 g_q_l[(size_t)MM*CC];
__device__ __align__(16) __nv_bfloat16 g_k_h[(size_t)MM*CC];
__device__ __align__(16) __nv_bfloat16 g_k_l[(size_t)MM*CC];
__device__ __align__(16) __nv_bfloat16 g_vt_h[(size_t)CC*MM];
__device__ __align__(16) __nv_bfloat16 g_vt_l[(size_t)CC*MM];
__device__ __align__(16) __nv_bfloat16 g_o_h[(size_t)MM*CC];
__device__ __align__(16) __nv_bfloat16 g_o_l[(size_t)MM*CC];

// ---------------- helpers ---------------------------------------------------
__device__ __forceinline__ void split1(float v, __nv_bfloat16& h, __nv_bfloat16& l) {
    h = __float2bfloat16(v);
    l = __float2bfloat16(v - __bfloat162float(h));
}

#define MMA(c,a,b) asm volatile( \
  "mma.sync.aligned.m16n8k16.row.col.f32.bf16.bf16.f32 " \
  "{%0,%1,%2,%3},{%4,%5,%6,%7},{%8,%9},{%0,%1,%2,%3};\n" \
  : "+f"((c)[0]),"+f"((c)[1]),"+f"((c)[2]),"+f"((c)[3]) \
  : "r"((a)[0]),"r"((a)[1]),"r"((a)[2]),"r"((a)[3]),"r"((b)[0]),"r"((b)[1]))

#define LDSM4(R0,R1,R2,R3,ADDR) asm volatile( \
  "ldmatrix.sync.aligned.m8n8.x4.shared.b16 {%0,%1,%2,%3},[%4];\n" \
  : "=r"(R0),"=r"(R1),"=r"(R2),"=r"(R3) : "r"(ADDR))

__device__ __forceinline__ void cpa16(uint32_t d, const void* s) {
    asm volatile("cp.async.cg.shared.global [%0], [%1], 16;\n" :: "r"(d), "l"(s));
}
#define CP_COMMIT() asm volatile("cp.async.commit_group;\n")
#define CP_WAIT1()  asm volatile("cp.async.wait_group 1;\n")
#define CP_WAIT0()  asm volatile("cp.async.wait_group 0;\n")

__device__ __forceinline__ uint32_t s2u(const void* p) {
    uint32_t a;
    asm("{ .reg .u64 t; cvta.to.shared.u64 t, %1; cvt.u32.u64 %0, t; }" : "=r"(a) : "l"(p));
    return a;
}

// ---------------- fp32 -> hi/lo bf16 convert --------------------------------
__global__ void conv_split(const float4* __restrict__ src,
                           __nv_bfloat162* __restrict__ h,
                           __nv_bfloat162* __restrict__ l, int n4)
{
    int i = blockIdx.x * blockDim.x + threadIdx.x;
    if (i >= n4) return;
    float4 v = src[i];
    __nv_bfloat162 h0, h1, l0, l1;
    split1(v.x, h0.x, l0.x); split1(v.y, h0.y, l0.y);
    split1(v.z, h1.x, l1.x); split1(v.w, h1.y, l1.y);
    h[(size_t)i*2]   = h0; h[(size_t)i*2+1] = h1;
    l[(size_t)i*2]   = l0; l[(size_t)i*2+1] = l1;
}

// ---------------------------------------------------------------------------
// bf16x3-split GEMM: C = epi(alpha * A @ B^T), A [M,K], B [N,K] (both K-major).
// A either pre-split planes (CONVA=0) or fp32 split at fill (CONVA=1).
// EPI: 0 = fp32 C (+bias), 1 = hi/lo plane C, 2 = sigmoid -> fp32 C.
// BM=128, 256 threads, warps 4x2, double-buffered cp.async, ldmatrix frags.
// ---------------------------------------------------------------------------
template<int BN, int EPI, int CONVA>
__global__ void __launch_bounds__(256, 2)
gemm_bf16x3(const __nv_bfloat16* __restrict__ Ahg, const __nv_bfloat16* __restrict__ Alg,
            const float* __restrict__ Afg, int lda, long aBS, long aHS,
            const __nv_bfloat16* __restrict__ Bhg, const __nv_bfloat16* __restrict__ Blg,
            int ldb, long bBS, long bHS,
            float* __restrict__ Cf, __nv_bfloat16* __restrict__ Ch,
            __nv_bfloat16* __restrict__ Cl, int ldc, long cBS, long cHS,
            int K, float alpha, const float* __restrict__ bias)
{
    constexpr int BM = 128;
    constexpr int SROW = 80;                    // bytes per 32-bf16 smem row
    constexpr int APL = BM * SROW;              // one A plane
    constexpr int BPL = BN * SROW;
    constexpr int PAH = 0, PAL = APL, PBH = 2*APL, PBL = 2*APL + BPL;
    constexpr int STG = 2*APL + 2*BPL;          // bytes per stage
    constexpr int WM = 32, WN = BN / 2;
    constexpr int MI = WM / 16, NJ = WN / 8;
    extern __shared__ uint8_t smem[];
    const uint32_t sb = s2u(smem);

    const int t = threadIdx.x, wid = t >> 5, lane = t & 31;
    const int wm = wid >> 1, wn = wid & 1;
    const int grp = lane >> 2, qid = lane & 3;

    const int z = blockIdx.z, zb = z / HH, zh = z % HH;
    const size_t aOff = (size_t)zb * aBS + (size_t)zh * aHS;
    const __nv_bfloat16* Ah = Ahg + aOff;
    const __nv_bfloat16* Al = Alg + aOff;
    const float*         Af = Afg + aOff;
    const __nv_bfloat16* Bh = Bhg + (size_t)zb * bBS + (size_t)zh * bHS;
    const __nv_bfloat16* Bl = Blg + (size_t)zb * bBS + (size_t)zh * bHS;
    const size_t cOff = (size_t)zb * cBS + (size_t)zh * cHS;

    const int bm = blockIdx.y * BM;
    const int bn = blockIdx.x * BN;

    // ldmatrix per-lane indices
    const int aRow  = (lane & 7) + ((lane >> 3) & 1) * 8;
    const int aHalf = lane >> 4;
    const int bRow  = ((lane >> 4) << 3) + (lane & 7);
    const int bHalf = (lane >> 3) & 1;

    float acc[MI][NJ][4];
    #pragma unroll
    for (int i = 0; i < MI; i++)
        #pragma unroll
        for (int j = 0; j < NJ; j++)
            #pragma unroll
            for (int c = 0; c < 4; c++) acc[i][j][c] = 0.f;

    auto fill = [&](int kt, int s) {
        const uint32_t sB = sb + s * STG;
        if (CONVA) {
            // fp32 A: load float4, split, STS 8B per plane
            #pragma unroll
            for (int it = 0; it < 4; it++) {
                int idx = it * 256 + t;
                int r = idx >> 3, q = idx & 7;
                float4 v = *(const float4*)(Af + (size_t)(bm + r) * lda + kt * 32 + q * 4);
                __nv_bfloat162 h0, h1, l0, l1;
                split1(v.x, h0.x, l0.x); split1(v.y, h0.y, l0.y);
                split1(v.z, h1.x, l1.x); split1(v.w, h1.y, l1.y);
                uint8_t* ph = smem + s * STG + PAH + r * SROW + q * 8;
                uint8_t* pl = smem + s * STG + PAL + r * SROW + q * 8;
                ((__nv_bfloat162*)ph)[0] = h0; ((__nv_bfloat162*)ph)[1] = h1;
                ((__nv_bfloat162*)pl)[0] = l0; ((__nv_bfloat162*)pl)[1] = l1;
            }
        } else {
            #pragma unroll
            for (int it = 0; it < 2; it++) {
                int idx = it * 256 + t;
                int r = idx >> 2, c = idx & 3;
                size_t g = ((size_t)(bm + r) * lda + kt * 32) * 2 + c * 16;
                uint32_t sm = r * SROW + c * 16;
                cpa16(sB + PAH + sm, (const uint8_t*)Ah + g);
                cpa16(sB + PAL + sm, (const uint8_t*)Al + g);
            }
        }
        #pragma unroll
        for (int it = 0; it < (BN * 4) / 256; it++) {
            int idx = it * 256 + t;
            int r = idx >> 2, c = idx & 3;
            size_t g = ((size_t)(bn + r) * ldb + kt * 32) * 2 + c * 16;
            uint32_t sm = r * SROW + c * 16;
            cpa16(sB + PBH + sm, (const uint8_t*)Bh + g);
            cpa16(sB + PBL + sm, (const uint8_t*)Bl + g);
        }
    };

    auto compute = [&](int s) {
        const uint32_t sB = sb + s * STG;
        const uint32_t aBase = sB + (wm * WM + aRow) * SROW + aHalf * 16;
        const uint32_t bBase = sB + (wn * WN + bRow) * SROW + bHalf * 16;
        #pragma unroll
        for (int kb = 0; kb < 32; kb += 16) {
            const uint32_t kof = kb * 2;
            uint32_t ah[MI][4], al[MI][4], bx[NJ][2];
            #pragma unroll
            for (int i = 0; i < MI; i++)
                LDSM4(ah[i][0], ah[i][1], ah[i][2], ah[i][3],
                      aBase + PAH + i * 16 * SROW + kof);
            #pragma unroll
            for (int jg = 0; jg < NJ / 2; jg++)
                LDSM4(bx[2*jg][0], bx[2*jg][1], bx[2*jg+1][0], bx[2*jg+1][1],
                      bBase + PBH + jg * 16 * SROW + kof);
            #pragma unroll
            for (int i = 0; i < MI; i++)
                #pragma unroll
                for (int j = 0; j < NJ; j++) MMA(acc[i][j], ah[i], bx[j]);
            #pragma unroll
            for (int i = 0; i < MI; i++)
                LDSM4(al[i][0], al[i][1], al[i][2], al[i][3],
                      aBase + PAL + i * 16 * SROW + kof);
            #pragma unroll
            for (int i = 0; i < MI; i++)
                #pragma unroll
                for (int j = 0; j < NJ; j++) MMA(acc[i][j], al[i], bx[j]);
            #pragma unroll
            for (int jg = 0; jg < NJ / 2; jg++)
                LDSM4(bx[2*jg][0], bx[2*jg][1], bx[2*jg+1][0], bx[2*jg+1][1],
                      bBase + PBL + jg * 16 * SROW + kof);
            #pragma unroll
            for (int i = 0; i < MI; i++)
                #pragma unroll
                for (int j = 0; j < NJ; j++) MMA(acc[i][j], ah[i], bx[j]);
        }
    };

    const int KT = K >> 5;
    fill(0, 0);
    CP_COMMIT();
    for (int kt = 0; kt < KT; kt++) {
        int s = kt & 1;
        if (kt + 1 < KT) { fill(kt + 1, s ^ 1); CP_COMMIT(); CP_WAIT1(); }
        else             { CP_WAIT0(); }
        __syncthreads();
        compute(s);
        __syncthreads();
    }

    // ---- epilogue ----
    #pragma unroll
    for (int i = 0; i < MI; i++) {
        int r0 = bm + wm * WM + i * 16 + grp;
        #pragma unroll
        for (int j = 0; j < NJ; j++) {
            int c0 = bn + wn * WN + j * 8 + qid * 2;
            float v0 = acc[i][j][0] * alpha;
            float v1 = acc[i][j][1] * alpha;
            float v2 = acc[i][j][2] * alpha;
            float v3 = acc[i][j][3] * alpha;
            if (EPI == 2) {
                v0 = 1.f / (1.f + __expf(-v0));
                v1 = 1.f / (1.f + __expf(-v1));
                v2 = 1.f / (1.f + __expf(-v2));
                v3 = 1.f / (1.f + __expf(-v3));
            }
            if (EPI == 0 && bias) {
                float b0 = bias[c0], b1 = bias[c0 + 1];
                v0 += b0; v1 += b1; v2 += b0; v3 += b1;
            }
            if (EPI == 0 || EPI == 2) {
                float* p0 = Cf + cOff + (size_t)r0 * ldc + c0;
                float* p1 = Cf + cOff + (size_t)(r0 + 8) * ldc + c0;
                p0[0] = v0; p0[1] = v1; p1[0] = v2; p1[1] = v3;
            }
            if (EPI == 1) {
                __nv_bfloat162 h0, l0, h1, l1;
                split1(v0, h0.x, l0.x); split1(v1, h0.y, l0.y);
                split1(v2, h1.x, l1.x); split1(v3, h1.y, l1.y);
                size_t o0 = cOff + (size_t)r0 * ldc + c0;
                size_t o1 = cOff + (size_t)(r0 + 8) * ldc + c0;
                *(__nv_bfloat162*)(Ch + o0) = h0;
                *(__nv_bfloat162*)(Cl + o0) = l0;
                *(__nv_bfloat162*)(Ch + o1) = h1;
                *(__nv_bfloat162*)(Cl + o1) = l1;
            }
        }
    }
}

// ---------------------------------------------------------------------------
extern "C" void kernel_launch(void* const* d_in, const int* in_sizes, int n_in,
                              void* d_out, int out_size)
{
    const float* x_q = (const float*)d_in[0];
    const float* x_k = (const float*)d_in[1];
    const float* x_v = (const float*)d_in[2];
    const float* Wq  = (const float*)d_in[3];
    const float* Wk  = (const float*)d_in[4];
    const float* Wv  = (const float*)d_in[5];
    const float* Wp  = (const float*)d_in[6];
    const float* bp  = (const float*)d_in[7];

    __nv_bfloat16 *xvh, *xvl, *wqh, *wql, *wkh, *wkl, *wph, *wpl;
    __nv_bfloat16 *qh, *ql, *kh, *kl, *vth, *vtl, *oh, *ol;
    cudaGetSymbolAddress((void**)&xvh, g_xv_h); cudaGetSymbolAddress((void**)&xvl, g_xv_l);
    cudaGetSymbolAddress((void**)&wqh, g_wq_h); cudaGetSymbolAddress((void**)&wql, g_wq_l);
    cudaGetSymbolAddress((void**)&wkh, g_wk_h); cudaGetSymbolAddress((void**)&wkl, g_wk_l);
    cudaGetSymbolAddress((void**)&wph, g_wp_h); cudaGetSymbolAddress((void**)&wpl, g_wp_l);
    cudaGetSymbolAddress((void**)&qh,  g_q_h);  cudaGetSymbolAddress((void**)&ql,  g_q_l);
    cudaGetSymbolAddress((void**)&kh,  g_k_h);  cudaGetSymbolAddress((void**)&kl,  g_k_l);
    cudaGetSymbolAddress((void**)&vth, g_vt_h); cudaGetSymbolAddress((void**)&vtl, g_vt_l);
    cudaGetSymbolAddress((void**)&oh,  g_o_h);  cudaGetSymbolAddress((void**)&ol,  g_o_l);

    float* out  = (float*)d_out;
    float* attn = out + (size_t)MM * CC;

    const int SM128 = 2 * (2 * 128 * 80 + 2 * 128 * 80);  // 81920
    const int SM64  = 2 * (2 * 128 * 80 + 2 * 64  * 80);  // 61440
    cudaFuncSetAttribute(gemm_bf16x3<128,1,1>, cudaFuncAttributeMaxDynamicSharedMemorySize, SM128);
    cudaFuncSetAttribute(gemm_bf16x3<128,2,0>, cudaFuncAttributeMaxDynamicSharedMemorySize, SM128);
    cudaFuncSetAttribute(gemm_bf16x3<64, 1,1>, cudaFuncAttributeMaxDynamicSharedMemorySize, SM64);
    cudaFuncSetAttribute(gemm_bf16x3<128,0,0>, cudaFuncAttributeMaxDynamicSharedMemorySize, SM128);

    dim3 blk(256);

    // input conversions (B-side operands need bf16 planes)
    {
        int n4x = (MM * CC) / 4, n4w = (CC * CC) / 4;
        conv_split<<<(n4x + 255) / 256, 256>>>((const float4*)x_v,
            (__nv_bfloat162*)xvh, (__nv_bfloat162*)xvl, n4x);
        conv_split<<<(n4w + 255) / 256, 256>>>((const float4*)Wq,
            (__nv_bfloat162*)wqh, (__nv_bfloat162*)wql, n4w);
        conv_split<<<(n4w + 255) / 256, 256>>>((const float4*)Wk,
            (__nv_bfloat162*)wkh, (__nv_bfloat162*)wkl, n4w);
        conv_split<<<(n4w + 255) / 256, 256>>>((const float4*)Wp,
            (__nv_bfloat162*)wph, (__nv_bfloat162*)wpl, n4w);
    }

    // q = x_q @ Wq^T  (A fp32 split-at-fill, out planes)
    gemm_bf16x3<128,1,1><<<dim3(CC/128, MM/128, 1), blk, SM128>>>(
        nullptr, nullptr, x_q, CC, 0, 0, wqh, wql, CC, 0, 0,
        nullptr, qh, ql, CC, 0, 0, CC, 1.f, nullptr);
    // k = x_k @ Wk^T
    gemm_bf16x3<128,1,1><<<dim3(CC/128, MM/128, 1), blk, SM128>>>(
        nullptr, nullptr, x_k, CC, 0, 0, wkh, wkl, CC, 0, 0,
        nullptr, kh, kl, CC, 0, 0, CC, 1.f, nullptr);
    // vt = Wv @ x_v^T  (= v^T, [CC x MM])
    gemm_bf16x3<128,1,1><<<dim3(MM/128, CC/128, 1), blk, SM128>>>(
        nullptr, nullptr, Wv, CC, 0, 0, xvh, xvl, CC, 0, 0,
        nullptr, vth, vtl, MM, 0, 0, CC, 1.f, nullptr);

    // attn = sigmoid(q k^T / 8) per head -> fp32 d_out
    gemm_bf16x3<128,2,0><<<dim3(NSEQ/128, NSEQ/128, BB*HH), blk, SM128>>>(
        qh, ql, nullptr, CC, (long)NSEQ*CC, DD,
        kh, kl, CC, (long)NSEQ*CC, DD,
        attn, nullptr, nullptr, NSEQ, (long)HH*NSEQ*NSEQ, (long)NSEQ*NSEQ,
        DD, 0.125f, nullptr);

    // o = attn @ vt^T per head (A = attn fp32 split-at-fill, B = vt planes)
    gemm_bf16x3<64,1,1><<<dim3(1, NSEQ/128, BB*HH), blk, SM64>>>(
        nullptr, nullptr, attn, NSEQ, (long)HH*NSEQ*NSEQ, (long)NSEQ*NSEQ,
        vth, vtl, MM, NSEQ, (long)DD*MM,
        nullptr, oh, ol, CC, (long)NSEQ*CC, DD, NSEQ, 1.f, nullptr);

    // out = o @ Wp^T + bp
    gemm_bf16x3<128,0,0><<<dim3(CC/128, MM/128, 1), blk, SM128>>>(
        oh, ol, nullptr, CC, 0, 0, wph, wpl, CC, 0, 0,
        out, nullptr, nullptr, CC, 0, 0, CC, 1.f, bp);
}